// round 7
// baseline (speedup 1.0000x reference)
#include <cuda_runtime.h>
#include <cuda_bf16.h>

#define NB 4
#define NC 128
#define HWP (512*512)
#define NL 512
#define TILE 4096
#define THREADS 512

__device__ int g_counts[NB * NL];
__device__ int g_lab64;   // 1 if labels are int64, 0 if int32

__device__ __forceinline__ void red4(float* p, float a, float b, float c, float d) {
    asm volatile("red.global.add.v4.f32 [%0], {%1,%2,%3,%4};"
                 :: "l"(p), "f"(a), "f"(b), "f"(c), "f"(d) : "memory");
}

__global__ void zero_kernel(float* __restrict__ out, const unsigned int* __restrict__ lab32) {
    int i = blockIdx.x * 256 + threadIdx.x;
    if (i == 0) {
        // dtype probe: int64-LE labels in [0,512) have all odd 32-bit words == 0
        int is64 = 1;
        for (int k = 0; k < 128; k++) {
            if (lab32[2 * k + 1] != 0u || lab32[2 * k] >= 512u) { is64 = 0; break; }
        }
        g_lab64 = is64;
    }
    if (i < NB * NL * NC) out[i] = 0.0f;
    if (i < NB * NL) g_counts[i] = 0;
}

__global__ __launch_bounds__(THREADS, 2) void accum_kernel(
    const float* __restrict__ x,
    const void* __restrict__ lab_raw,
    float* __restrict__ out)
{
    __shared__ float bins[2][4 * NL];   // [buf][channel-of-group][label], 16 KB
    __shared__ int hist[NL];

    const int b   = blockIdx.y;
    const int p0  = blockIdx.x * TILE;
    const int tid = threadIdx.x;

    // zero bins + hist
    #pragma unroll
    for (int i = tid; i < 4 * NL; i += THREADS) { bins[0][i] = 0.f; bins[1][i] = 0.f; }
    hist[tid] = 0;   // THREADS == NL

    // ---- load this thread's 8 pixel labels into registers (fixed for all cgs) ----
    int lab[8];
    if (g_lab64) {
        const long long* lb = (const long long*)lab_raw + (size_t)b * HWP + p0;
        #pragma unroll
        for (int h = 0; h < 2; h++) {
            int q = tid + h * THREADS;
            #pragma unroll
            for (int j = 0; j < 4; j++)
                lab[4 * h + j] = ((int)lb[4 * q + j]) & (NL - 1);
        }
    } else {
        const int4* lb = (const int4*)((const int*)lab_raw + (size_t)b * HWP + p0);
        #pragma unroll
        for (int h = 0; h < 2; h++) {
            int4 v = lb[tid + h * THREADS];
            lab[4 * h + 0] = v.x & (NL - 1);
            lab[4 * h + 1] = v.y & (NL - 1);
            lab[4 * h + 2] = v.z & (NL - 1);
            lab[4 * h + 3] = v.w & (NL - 1);
        }
    }
    __syncthreads();   // bins/hist zeroed

    // ---- per-tile histogram -> global counts ----
    #pragma unroll
    for (int k = 0; k < 8; k++) atomicAdd(&hist[lab[k]], 1);
    __syncthreads();
    if (hist[tid]) atomicAdd(&g_counts[b * NL + tid], hist[tid]);

    // ---- main loop: direct atomic binning, double-buffered flush ----
    const float* xb = x + (size_t)b * NC * HWP + p0;
    float*       ob = out + (size_t)b * NL * NC;

    int cur = 0;
    #pragma unroll 1
    for (int cg = 0; cg < NC / 4; cg++) {
        const float* xp = xb + (size_t)(4 * cg) * HWP;
        float* bn = bins[cur];

        #pragma unroll
        for (int h = 0; h < 2; h++) {
            int q = tid + h * THREADS;
            const float4 a0 = *(const float4*)(xp + 4 * q);
            const float4 a1 = *(const float4*)(xp + (size_t)HWP     + 4 * q);
            const float4 a2 = *(const float4*)(xp + (size_t)2 * HWP + 4 * q);
            const float4 a3 = *(const float4*)(xp + (size_t)3 * HWP + 4 * q);

            const float v0[4] = {a0.x, a1.x, a2.x, a3.x};
            const float v1[4] = {a0.y, a1.y, a2.y, a3.y};
            const float v2[4] = {a0.z, a1.z, a2.z, a3.z};
            const float v3[4] = {a0.w, a1.w, a2.w, a3.w};

            int l0 = lab[4 * h], l1 = lab[4 * h + 1], l2 = lab[4 * h + 2], l3 = lab[4 * h + 3];
            #pragma unroll
            for (int c = 0; c < 4; c++) {
                atomicAdd(&bn[c * NL + l0], v0[c]);
                atomicAdd(&bn[c * NL + l1], v1[c]);
                atomicAdd(&bn[c * NL + l2], v2[c]);
                atomicAdd(&bn[c * NL + l3], v3[c]);
            }
        }
        __syncthreads();   // all atomics for this cg landed

        // flush bins[cur] (uniform: one label per thread), overlaps next cg's atomics
        {
            float c0 = bn[0 * NL + tid];
            float c1 = bn[1 * NL + tid];
            float c2 = bn[2 * NL + tid];
            float c3 = bn[3 * NL + tid];
            red4(ob + tid * NC + 4 * cg, c0, c1, c2, c3);
            bn[0 * NL + tid] = 0.f;
            bn[1 * NL + tid] = 0.f;
            bn[2 * NL + tid] = 0.f;
            bn[3 * NL + tid] = 0.f;
        }
        cur ^= 1;
    }
}

__global__ void finalize_kernel(float* __restrict__ out) {
    int i = blockIdx.x * 256 + threadIdx.x;
    if (i >= NB * NL * NC) return;
    int bl = i / NC;
    int c = g_counts[bl];
    float cnt = (float)(c > 1 ? c : 1);
    out[i] = out[i] / cnt;
}

extern "C" void kernel_launch(void* const* d_in, const int* in_sizes, int n_in,
                              void* d_out, int out_size) {
    // Resolve input binding by element count — x has 134217728 elements,
    // label_maps has 1048576. Do not trust ordering.
    const float* x;
    const void*  lab;
    if (in_sizes[0] > in_sizes[1]) {
        x   = (const float*)d_in[0];
        lab = d_in[1];
    } else {
        x   = (const float*)d_in[1];
        lab = d_in[0];
    }
    float* out = (float*)d_out;

    int ztot = NB * NL * NC;  // 262144
    zero_kernel<<<(ztot + 255) / 256, 256>>>(out, (const unsigned int*)lab);

    dim3 grid(HWP / TILE, NB);  // 64 x 4 = 256 CTAs, one wave at 2 CTA/SM
    accum_kernel<<<grid, THREADS>>>(x, lab, out);

    finalize_kernel<<<(ztot + 255) / 256, 256>>>(out);
}

// round 9
// speedup vs baseline: 1.4102x; 1.4102x over previous
#include <cuda_runtime.h>
#include <cuda_bf16.h>

#define NB 4
#define NC 128
#define HWP (512*512)
#define NL 512
#define TILE 4096
#define THREADS 512
#define DEPTH 4

// dynamic smem offsets (bytes)
#define OFF_RING   0                    // float ring[4][TILE]  = 65536
#define OFF_ENT    65536                // uint  ent[TILE]      = 16384
#define OFF_BINS   81920                // float bins[2][2048]  = 16384
#define OFF_CNT    98304                // int cnt[NL]          = 2048
#define OFF_START  100352               // int start[NL]        = 2048
#define OFF_CURSOR 102400               // int cursor[NL]       = 2048
#define OFF_WSUM   104448               // int wsum[16]         = 64
#define SMEM_BYTES 104512

__device__ int g_counts[NB * NL];
__device__ int g_lab64;   // 1 if labels are int64, 0 if int32

__device__ __forceinline__ void red4(float* p, float a, float b, float c, float d) {
    asm volatile("red.global.add.v4.f32 [%0], {%1,%2,%3,%4};"
                 :: "l"(p), "f"(a), "f"(b), "f"(c), "f"(d) : "memory");
}
__device__ __forceinline__ void cpasync16(unsigned int s, const void* g) {
    asm volatile("cp.async.cg.shared.global [%0], [%1], 16;" :: "r"(s), "l"(g));
}
#define CP_COMMIT() asm volatile("cp.async.commit_group;")
#define CP_WAIT(n)  asm volatile("cp.async.wait_group %0;" :: "n"(n))

// stage one channel plane (TILE floats) into ring slot, then commit
__device__ __forceinline__ void issue_ch(unsigned int ring_u32, int slot,
                                         const float* src, int tid) {
    unsigned int s = ring_u32 + slot * (TILE * 4) + tid * 16;
    cpasync16(s,        src + 4 * tid);
    cpasync16(s + 8192, src + 4 * tid + TILE / 2);
    CP_COMMIT();
}

__global__ void zero_kernel(float* __restrict__ out, const unsigned int* __restrict__ lab32) {
    int i = blockIdx.x * 256 + threadIdx.x;
    if (i == 0) {
        // dtype probe: int64-LE labels in [0,512) have all odd 32-bit words == 0
        int is64 = 1;
        for (int k = 0; k < 128; k++) {
            if (lab32[2 * k + 1] != 0u || lab32[2 * k] >= 512u) { is64 = 0; break; }
        }
        g_lab64 = is64;
    }
    if (i < NB * NL * NC) out[i] = 0.0f;
    if (i < NB * NL) g_counts[i] = 0;
}

__global__ __launch_bounds__(THREADS, 2) void accum_kernel(
    const float* __restrict__ x,
    const void* __restrict__ lab_raw,
    float* __restrict__ out)
{
    extern __shared__ char smem[];
    float*        ring   = (float*)(smem + OFF_RING);
    unsigned int* ent    = (unsigned int*)(smem + OFF_ENT);
    float*        bins   = (float*)(smem + OFF_BINS);
    int*          cnt    = (int*)(smem + OFF_CNT);
    int*          start_ = (int*)(smem + OFF_START);
    int*          cursor = (int*)(smem + OFF_CURSOR);
    int*          wsum   = (int*)(smem + OFF_WSUM);

    const int b    = blockIdx.y;
    const int p0   = blockIdx.x * TILE;
    const int tid  = threadIdx.x;
    const int lane = tid & 31;
    const int wid  = tid >> 5;

    const unsigned int ring_u32 =
        (unsigned int)__cvta_generic_to_shared(smem) + OFF_RING;
    const float* xb = x + (size_t)b * NC * HWP + p0;

    // deep prefetch of channels 0..3 — overlaps the whole sort prologue
    #pragma unroll
    for (int s = 0; s < DEPTH; s++)
        issue_ch(ring_u32, s, xb + (size_t)s * HWP, tid);

    // ---- labels into registers ----
    int lab[8];
    if (g_lab64) {
        const long long* lb = (const long long*)lab_raw + (size_t)b * HWP + p0;
        #pragma unroll
        for (int h = 0; h < 2; h++) {
            int q = tid + h * THREADS;
            #pragma unroll
            for (int j = 0; j < 4; j++)
                lab[4 * h + j] = ((int)lb[4 * q + j]) & (NL - 1);
        }
    } else {
        const int4* lb = (const int4*)((const int*)lab_raw + (size_t)b * HWP + p0);
        #pragma unroll
        for (int h = 0; h < 2; h++) {
            int4 vv = lb[tid + h * THREADS];
            lab[4 * h + 0] = vv.x & (NL - 1);
            lab[4 * h + 1] = vv.y & (NL - 1);
            lab[4 * h + 2] = vv.z & (NL - 1);
            lab[4 * h + 3] = vv.w & (NL - 1);
        }
    }

    // ---- zero cnt + bins ----
    cnt[tid] = 0;                               // THREADS == NL
    #pragma unroll
    for (int k = 0; k < 8; k++) bins[k * NL + tid] = 0.f;   // 2*2048 floats
    __syncthreads();

    // ---- histogram ----
    #pragma unroll
    for (int k = 0; k < 8; k++) atomicAdd(&cnt[lab[k]], 1);
    __syncthreads();

    // ---- exclusive prefix sum over cnt[512] ----
    int v = cnt[tid];
    int s = v;
    #pragma unroll
    for (int d = 1; d < 32; d <<= 1) {
        int n2 = __shfl_up_sync(0xffffffffu, s, d);
        if (lane >= d) s += n2;
    }
    if (lane == 31) wsum[wid] = s;
    __syncthreads();
    if (tid < 16) {
        int t = wsum[tid];
        #pragma unroll
        for (int d = 1; d < 16; d <<= 1) {
            int n2 = __shfl_up_sync(0x0000ffffu, t, d);
            if ((int)tid >= d) t += n2;
        }
        wsum[tid] = t;
    }
    __syncthreads();
    int excl = s - v + (wid ? wsum[wid - 1] : 0);
    start_[tid]  = excl;
    cursor[tid]  = excl;
    if (v) atomicAdd(&g_counts[b * NL + tid], v);
    __syncthreads();

    // ---- scatter packed entries (label<<12 | pixel), sorted by label ----
    #pragma unroll
    for (int h = 0; h < 2; h++) {
        #pragma unroll
        for (int j = 0; j < 4; j++) {
            int k   = 4 * h + j;
            int pix = 4 * (tid + h * THREADS) + j;
            int l   = lab[k];
            int pos = atomicAdd(&cursor[l], 1);
            ent[pos] = ((unsigned int)l << 12) | (unsigned int)pix;
        }
    }
    __syncthreads();

    // ---- each thread owns 8 consecutive sorted entries (perfectly balanced) ----
    unsigned int er[8];
    {
        uint4 e0 = *(const uint4*)(ent + 8 * tid);
        uint4 e1 = *(const uint4*)(ent + 8 * tid + 4);
        er[0] = e0.x; er[1] = e0.y; er[2] = e0.z; er[3] = e0.w;
        er[4] = e1.x; er[5] = e1.y; er[6] = e1.z; er[7] = e1.w;
    }

    // ---- channel loop: depth-4 pipeline, segmented register accumulation ----
    float* ob = out + (size_t)b * NL * NC;
    int bb = 0;

    #pragma unroll 1
    for (int c = 0; c < NC; c++) {
        int rem = NC - 1 - c;
        if (rem >= 3)      { CP_WAIT(3); }
        else if (rem == 2) { CP_WAIT(2); }
        else if (rem == 1) { CP_WAIT(1); }
        else               { CP_WAIT(0); }
        __syncthreads();

        const float* buf = ring + (c & 3) * TILE;
        float* bnc = bins + bb * 2048 + (c & 3) * NL;

        float vv[8];
        #pragma unroll
        for (int j = 0; j < 8; j++) vv[j] = buf[er[j] & 4095u];

        float a = vv[0];
        unsigned int pl = er[0] >> 12;
        #pragma unroll
        for (int j = 1; j < 8; j++) {
            unsigned int l = er[j] >> 12;
            if (l != pl) { atomicAdd(&bnc[pl], a); a = vv[j]; pl = l; }
            else a += vv[j];
        }
        atomicAdd(&bnc[pl], a);
        __syncthreads();

        if (c + DEPTH < NC)
            issue_ch(ring_u32, c & 3, xb + (size_t)(c + DEPTH) * HWP, tid);

        if ((c & 3) == 3) {
            float* bn = bins + bb * 2048;
            red4(ob + tid * NC + (c - 3),
                 bn[tid], bn[NL + tid], bn[2 * NL + tid], bn[3 * NL + tid]);
            bn[tid] = 0.f; bn[NL + tid] = 0.f;
            bn[2 * NL + tid] = 0.f; bn[3 * NL + tid] = 0.f;
            bb ^= 1;
        }
    }
}

__global__ void finalize_kernel(float* __restrict__ out) {
    int i = blockIdx.x * 256 + threadIdx.x;
    if (i >= NB * NL * NC) return;
    int bl = i / NC;
    int c = g_counts[bl];
    float cnt = (float)(c > 1 ? c : 1);
    out[i] = out[i] / cnt;
}

extern "C" void kernel_launch(void* const* d_in, const int* in_sizes, int n_in,
                              void* d_out, int out_size) {
    // Resolve input binding by element count — x has 134217728 elements,
    // label_maps has 1048576. Do not trust ordering.
    const float* x;
    const void*  lab;
    if (in_sizes[0] > in_sizes[1]) {
        x   = (const float*)d_in[0];
        lab = d_in[1];
    } else {
        x   = (const float*)d_in[1];
        lab = d_in[0];
    }
    float* out = (float*)d_out;

    cudaFuncSetAttribute(accum_kernel,
                         cudaFuncAttributeMaxDynamicSharedMemorySize, SMEM_BYTES);

    int ztot = NB * NL * NC;  // 262144
    zero_kernel<<<(ztot + 255) / 256, 256>>>(out, (const unsigned int*)lab);

    dim3 grid(HWP / TILE, NB);  // 64 x 4 = 256 CTAs, one wave at 2 CTA/SM
    accum_kernel<<<grid, THREADS, SMEM_BYTES>>>(x, lab, out);

    finalize_kernel<<<(ztot + 255) / 256, 256>>>(out);
}

// round 10
// speedup vs baseline: 1.4613x; 1.0363x over previous
#include <cuda_runtime.h>
#include <cuda_bf16.h>

#define NB 4
#define NC 128
#define HWP (512*512)
#define NL 512
#define TILE 4096
#define THREADS 512
#define DEPTH 4
#define PLANEB (TILE * 4)

// dynamic smem offsets (bytes)
#define OFF_RING   0                    // float ring[4][TILE]  = 65536
#define OFF_ENT    65536                // uint  ent[TILE]      = 16384
#define OFF_BINS   81920                // float bins[2][2048]  = 16384
#define OFF_CNT    98304                // int cnt[NL]          = 2048
#define OFF_START  100352               // int start[NL]        = 2048
#define OFF_CURSOR 102400               // int cursor[NL]       = 2048
#define OFF_WSUM   104448               // int wsum[16]         = 64
#define OFF_MBAR   104512               // uint64 mbar[4]       = 32
#define SMEM_BYTES 104576

__device__ int g_counts[NB * NL];
__device__ int g_lab64;   // 1 if labels are int64, 0 if int32

__device__ __forceinline__ void red4(float* p, float a, float b, float c, float d) {
    asm volatile("red.global.add.v4.f32 [%0], {%1,%2,%3,%4};"
                 :: "l"(p), "f"(a), "f"(b), "f"(c), "f"(d) : "memory");
}
__device__ __forceinline__ void mbar_init(unsigned int a, unsigned int cnt) {
    asm volatile("mbarrier.init.shared.b64 [%0], %1;" :: "r"(a), "r"(cnt) : "memory");
}
__device__ __forceinline__ void mbar_expect_tx(unsigned int a, unsigned int bytes) {
    asm volatile("mbarrier.arrive.expect_tx.shared.b64 _, [%0], %1;"
                 :: "r"(a), "r"(bytes) : "memory");
}
__device__ __forceinline__ void mbar_wait(unsigned int a, unsigned int parity) {
    asm volatile(
        "{\n\t"
        ".reg .pred P1;\n\t"
        "WAIT_LOOP_%=:\n\t"
        "mbarrier.try_wait.parity.acquire.cta.shared::cta.b64 P1, [%0], %1, 0x989680;\n\t"
        "@P1 bra.uni WAIT_DONE_%=;\n\t"
        "bra.uni WAIT_LOOP_%=;\n\t"
        "WAIT_DONE_%=:\n\t"
        "}"
        :: "r"(a), "r"(parity) : "memory");
}
// bulk async copy GMEM -> SMEM, completion via mbarrier complete_tx
__device__ __forceinline__ void bulk_g2s(unsigned int dst, const void* src,
                                         unsigned int bytes, unsigned int mbar) {
    asm volatile(
        "cp.async.bulk.shared::cta.global.mbarrier::complete_tx::bytes [%0], [%1], %2, [%3];"
        :: "r"(dst), "l"(src), "r"(bytes), "r"(mbar) : "memory");
}

__global__ void zero_kernel(float* __restrict__ out, const unsigned int* __restrict__ lab32) {
    int i = blockIdx.x * 256 + threadIdx.x;
    if (i == 0) {
        // dtype probe: int64-LE labels in [0,512) have all odd 32-bit words == 0
        int is64 = 1;
        for (int k = 0; k < 128; k++) {
            if (lab32[2 * k + 1] != 0u || lab32[2 * k] >= 512u) { is64 = 0; break; }
        }
        g_lab64 = is64;
    }
    if (i < NB * NL * NC) out[i] = 0.0f;
    if (i < NB * NL) g_counts[i] = 0;
}

__global__ __launch_bounds__(THREADS, 2) void accum_kernel(
    const float* __restrict__ x,
    const void* __restrict__ lab_raw,
    float* __restrict__ out)
{
    extern __shared__ char smem[];
    float*        ring   = (float*)(smem + OFF_RING);
    unsigned int* ent    = (unsigned int*)(smem + OFF_ENT);
    float*        bins   = (float*)(smem + OFF_BINS);
    int*          cnt    = (int*)(smem + OFF_CNT);
    int*          start_ = (int*)(smem + OFF_START);
    int*          cursor = (int*)(smem + OFF_CURSOR);
    int*          wsum   = (int*)(smem + OFF_WSUM);

    const int b    = blockIdx.y;
    const int p0   = blockIdx.x * TILE;
    const int tid  = threadIdx.x;
    const int lane = tid & 31;
    const int wid  = tid >> 5;

    const unsigned int smem_u32 = (unsigned int)__cvta_generic_to_shared(smem);
    const unsigned int ring_u32 = smem_u32 + OFF_RING;
    const unsigned int mbar_u32 = smem_u32 + OFF_MBAR;
    const float* xb = x + (size_t)b * NC * HWP + p0;

    // ---- init mbarriers, then deep-prefetch channels 0..3 via bulk-async ----
    if (tid == 0) {
        #pragma unroll
        for (int s = 0; s < DEPTH; s++) mbar_init(mbar_u32 + 8 * s, 1);
    }
    __syncthreads();
    if (tid == 0) {
        #pragma unroll
        for (int s = 0; s < DEPTH; s++) {
            mbar_expect_tx(mbar_u32 + 8 * s, PLANEB);
            bulk_g2s(ring_u32 + s * PLANEB, xb + (size_t)s * HWP, PLANEB, mbar_u32 + 8 * s);
        }
    }

    // ---- labels into registers (overlaps the in-flight bulk copies) ----
    int lab[8];
    if (g_lab64) {
        const long long* lb = (const long long*)lab_raw + (size_t)b * HWP + p0;
        #pragma unroll
        for (int h = 0; h < 2; h++) {
            int q = tid + h * THREADS;
            #pragma unroll
            for (int j = 0; j < 4; j++)
                lab[4 * h + j] = ((int)lb[4 * q + j]) & (NL - 1);
        }
    } else {
        const int4* lb = (const int4*)((const int*)lab_raw + (size_t)b * HWP + p0);
        #pragma unroll
        for (int h = 0; h < 2; h++) {
            int4 vv = lb[tid + h * THREADS];
            lab[4 * h + 0] = vv.x & (NL - 1);
            lab[4 * h + 1] = vv.y & (NL - 1);
            lab[4 * h + 2] = vv.z & (NL - 1);
            lab[4 * h + 3] = vv.w & (NL - 1);
        }
    }

    // ---- zero cnt + bins ----
    cnt[tid] = 0;                               // THREADS == NL
    #pragma unroll
    for (int k = 0; k < 8; k++) bins[k * NL + tid] = 0.f;
    __syncthreads();

    // ---- histogram ----
    #pragma unroll
    for (int k = 0; k < 8; k++) atomicAdd(&cnt[lab[k]], 1);
    __syncthreads();

    // ---- exclusive prefix sum over cnt[512] ----
    int v = cnt[tid];
    int s = v;
    #pragma unroll
    for (int d = 1; d < 32; d <<= 1) {
        int n2 = __shfl_up_sync(0xffffffffu, s, d);
        if (lane >= d) s += n2;
    }
    if (lane == 31) wsum[wid] = s;
    __syncthreads();
    if (tid < 16) {
        int t = wsum[tid];
        #pragma unroll
        for (int d = 1; d < 16; d <<= 1) {
            int n2 = __shfl_up_sync(0x0000ffffu, t, d);
            if ((int)tid >= d) t += n2;
        }
        wsum[tid] = t;
    }
    __syncthreads();
    int excl = s - v + (wid ? wsum[wid - 1] : 0);
    start_[tid]  = excl;
    cursor[tid]  = excl;
    if (v) atomicAdd(&g_counts[b * NL + tid], v);
    __syncthreads();

    // ---- scatter packed entries (label<<12 | pixel), sorted by label ----
    #pragma unroll
    for (int h = 0; h < 2; h++) {
        #pragma unroll
        for (int j = 0; j < 4; j++) {
            int k   = 4 * h + j;
            int pix = 4 * (tid + h * THREADS) + j;
            int l   = lab[k];
            int pos = atomicAdd(&cursor[l], 1);
            ent[pos] = ((unsigned int)l << 12) | (unsigned int)pix;
        }
    }
    __syncthreads();

    // ---- each thread owns 8 consecutive sorted entries (perfectly balanced) ----
    unsigned int er[8];
    {
        uint4 e0 = *(const uint4*)(ent + 8 * tid);
        uint4 e1 = *(const uint4*)(ent + 8 * tid + 4);
        er[0] = e0.x; er[1] = e0.y; er[2] = e0.z; er[3] = e0.w;
        er[4] = e1.x; er[5] = e1.y; er[6] = e1.z; er[7] = e1.w;
    }

    // ---- channel loop: depth-4 bulk-async ring, segmented register accumulation ----
    float* ob = out + (size_t)b * NL * NC;
    int bb = 0;

    #pragma unroll 1
    for (int c = 0; c < NC; c++) {
        const int slot = c & 3;
        const unsigned int mb = mbar_u32 + 8 * slot;
        mbar_wait(mb, (unsigned int)((c >> 2) & 1));   // data for channel c landed

        const float* buf = ring + slot * TILE;
        float* bnc = bins + bb * 2048 + slot * NL;

        float vv[8];
        #pragma unroll
        for (int j = 0; j < 8; j++) vv[j] = buf[er[j] & 4095u];

        float a = vv[0];
        unsigned int pl = er[0] >> 12;
        #pragma unroll
        for (int j = 1; j < 8; j++) {
            unsigned int l = er[j] >> 12;
            if (l != pl) { atomicAdd(&bnc[pl], a); a = vv[j]; pl = l; }
            else a += vv[j];
        }
        atomicAdd(&bnc[pl], a);
        __syncthreads();   // all threads done with ring[slot] and this channel's bins

        if (tid == 0 && c + DEPTH < NC) {   // refill slot for channel c+4
            mbar_expect_tx(mb, PLANEB);
            bulk_g2s(ring_u32 + slot * PLANEB, xb + (size_t)(c + DEPTH) * HWP, PLANEB, mb);
        }

        if (slot == 3) {
            float* bn = bins + bb * 2048;
            red4(ob + tid * NC + (c - 3),
                 bn[tid], bn[NL + tid], bn[2 * NL + tid], bn[3 * NL + tid]);
            bn[tid] = 0.f; bn[NL + tid] = 0.f;
            bn[2 * NL + tid] = 0.f; bn[3 * NL + tid] = 0.f;
            bb ^= 1;
        }
    }
}

__global__ void finalize_kernel(float* __restrict__ out) {
    int i = blockIdx.x * 256 + threadIdx.x;
    if (i >= NB * NL * NC) return;
    int bl = i / NC;
    int c = g_counts[bl];
    float cnt = (float)(c > 1 ? c : 1);
    out[i] = out[i] / cnt;
}

extern "C" void kernel_launch(void* const* d_in, const int* in_sizes, int n_in,
                              void* d_out, int out_size) {
    // Resolve input binding by element count — x has 134217728 elements,
    // label_maps has 1048576. Do not trust ordering.
    const float* x;
    const void*  lab;
    if (in_sizes[0] > in_sizes[1]) {
        x   = (const float*)d_in[0];
        lab = d_in[1];
    } else {
        x   = (const float*)d_in[1];
        lab = d_in[0];
    }
    float* out = (float*)d_out;

    cudaFuncSetAttribute(accum_kernel,
                         cudaFuncAttributeMaxDynamicSharedMemorySize, SMEM_BYTES);

    int ztot = NB * NL * NC;  // 262144
    zero_kernel<<<(ztot + 255) / 256, 256>>>(out, (const unsigned int*)lab);

    dim3 grid(HWP / TILE, NB);  // 64 x 4 = 256 CTAs, one wave at 2 CTA/SM
    accum_kernel<<<grid, THREADS, SMEM_BYTES>>>(x, lab, out);

    finalize_kernel<<<(ztot + 255) / 256, 256>>>(out);
}

// round 11
// speedup vs baseline: 1.7637x; 1.2069x over previous
#include <cuda_runtime.h>
#include <cuda_bf16.h>

#define NB 4
#define NC 128
#define HWP (512*512)
#define NL 512
#define TILE 4096
#define THREADS 512
#define NG (NC / 4)

// dynamic smem offsets (bytes)
#define OFF_SX     0        // float4 sx[TILE]     = 65536 (channel-interleaved, swizzled)
#define OFF_ENT    65536    // uint ent[TILE]      = 16384
#define OFF_CNT    81920    // int cnt[NL]         = 2048
#define OFF_START  83968    // int start[NL]       = 2048
#define OFF_CURSOR 86016    // int cursor[NL]      = 2048
#define OFF_WSUM   88064    // int wsum[16]        = 64
#define SMEM_BYTES 88128

__device__ int g_counts[NB * NL];
__device__ int g_lab64;   // 1 if labels are int64, 0 if int32

__device__ __forceinline__ void red4(float* p, float a, float b, float c, float d) {
    asm volatile("red.global.add.v4.f32 [%0], {%1,%2,%3,%4};"
                 :: "l"(p), "f"(a), "f"(b), "f"(c), "f"(d) : "memory");
}
__device__ __forceinline__ float4 lds128(unsigned int addr) {
    float4 v;
    asm volatile("ld.shared.v4.f32 {%0,%1,%2,%3}, [%4];"
                 : "=f"(v.x), "=f"(v.y), "=f"(v.z), "=f"(v.w) : "r"(addr));
    return v;
}
__device__ __forceinline__ void sts128(unsigned int addr, float a, float b, float c, float d) {
    asm volatile("st.shared.v4.f32 [%0], {%1,%2,%3,%4};"
                 :: "r"(addr), "f"(a), "f"(b), "f"(c), "f"(d));
}
__device__ __forceinline__ unsigned int swz(int pix) {   // 16B-slot swizzle (verified in R5)
    return (unsigned int)((pix ^ ((pix >> 3) & 7)) * 16);
}

__global__ void zero_kernel(float* __restrict__ out, const unsigned int* __restrict__ lab32) {
    int i = blockIdx.x * 256 + threadIdx.x;
    if (i == 0) {
        // dtype probe: int64-LE labels in [0,512) have all odd 32-bit words == 0
        int is64 = 1;
        for (int k = 0; k < 128; k++) {
            if (lab32[2 * k + 1] != 0u || lab32[2 * k] >= 512u) { is64 = 0; break; }
        }
        g_lab64 = is64;
    }
    if (i < NB * NL * NC) out[i] = 0.0f;
    if (i < NB * NL) g_counts[i] = 0;
}

__global__ __launch_bounds__(THREADS, 2) void accum_kernel(
    const float* __restrict__ x,
    const void* __restrict__ lab_raw,
    float* __restrict__ out)
{
    extern __shared__ char smem[];
    unsigned int* ent    = (unsigned int*)(smem + OFF_ENT);
    int*          cnt    = (int*)(smem + OFF_CNT);
    int*          start_ = (int*)(smem + OFF_START);
    int*          cursor = (int*)(smem + OFF_CURSOR);
    int*          wsum   = (int*)(smem + OFF_WSUM);

    const int b    = blockIdx.y;
    const int p0   = blockIdx.x * TILE;
    const int tid  = threadIdx.x;
    const int lane = tid & 31;
    const int wid  = tid >> 5;

    const unsigned int sx_base =
        (unsigned int)__cvta_generic_to_shared(smem) + OFF_SX;
    const float* xb = x + (size_t)b * NC * HWP + p0;

    // ---- prefetch group 0 into registers (overlaps the whole sort prologue) ----
    float4 pf[8];
    {
        const float* xp = xb;
        #pragma unroll
        for (int h = 0; h < 2; h++) {
            int q = tid + h * THREADS;
            pf[4 * h + 0] = *(const float4*)(xp + 4 * q);
            pf[4 * h + 1] = *(const float4*)(xp + (size_t)HWP     + 4 * q);
            pf[4 * h + 2] = *(const float4*)(xp + (size_t)2 * HWP + 4 * q);
            pf[4 * h + 3] = *(const float4*)(xp + (size_t)3 * HWP + 4 * q);
        }
    }

    // ---- labels into registers ----
    int lab[8];
    if (g_lab64) {
        const long long* lb = (const long long*)lab_raw + (size_t)b * HWP + p0;
        #pragma unroll
        for (int h = 0; h < 2; h++) {
            int q = tid + h * THREADS;
            #pragma unroll
            for (int j = 0; j < 4; j++)
                lab[4 * h + j] = ((int)lb[4 * q + j]) & (NL - 1);
        }
    } else {
        const int4* lb = (const int4*)((const int*)lab_raw + (size_t)b * HWP + p0);
        #pragma unroll
        for (int h = 0; h < 2; h++) {
            int4 vv = lb[tid + h * THREADS];
            lab[4 * h + 0] = vv.x & (NL - 1);
            lab[4 * h + 1] = vv.y & (NL - 1);
            lab[4 * h + 2] = vv.z & (NL - 1);
            lab[4 * h + 3] = vv.w & (NL - 1);
        }
    }

    cnt[tid] = 0;                               // THREADS == NL
    __syncthreads();

    // ---- histogram ----
    #pragma unroll
    for (int k = 0; k < 8; k++) atomicAdd(&cnt[lab[k]], 1);
    __syncthreads();

    // ---- exclusive prefix sum over cnt[512] ----
    int v = cnt[tid];
    int s = v;
    #pragma unroll
    for (int d = 1; d < 32; d <<= 1) {
        int n2 = __shfl_up_sync(0xffffffffu, s, d);
        if (lane >= d) s += n2;
    }
    if (lane == 31) wsum[wid] = s;
    __syncthreads();
    if (tid < 16) {
        int t = wsum[tid];
        #pragma unroll
        for (int d = 1; d < 16; d <<= 1) {
            int n2 = __shfl_up_sync(0x0000ffffu, t, d);
            if ((int)tid >= d) t += n2;
        }
        wsum[tid] = t;
    }
    __syncthreads();
    int excl = s - v + (wid ? wsum[wid - 1] : 0);
    start_[tid]  = excl;
    cursor[tid]  = excl;
    if (v) atomicAdd(&g_counts[b * NL + tid], v);
    __syncthreads();

    // ---- scatter packed entries (label<<12 | pixel), sorted by label ----
    #pragma unroll
    for (int h = 0; h < 2; h++) {
        #pragma unroll
        for (int j = 0; j < 4; j++) {
            int k   = 4 * h + j;
            int pix = 4 * (tid + h * THREADS) + j;
            int l   = lab[k];
            int pos = atomicAdd(&cursor[l], 1);
            ent[pos] = ((unsigned int)l << 12) | (unsigned int)pix;
        }
    }
    __syncthreads();

    // ---- each thread owns 8 consecutive sorted entries (perfectly balanced) ----
    unsigned int er[8];
    {
        uint4 e0 = *(const uint4*)(ent + 8 * tid);
        uint4 e1 = *(const uint4*)(ent + 8 * tid + 4);
        er[0] = e0.x; er[1] = e0.y; er[2] = e0.z; er[3] = e0.w;
        er[4] = e1.x; er[5] = e1.y; er[6] = e1.z; er[7] = e1.w;
    }

    // ---- channel-group loop: pipelined LDG->STS transpose, LDS.128 gather,
    //      run-boundary red4 straight to gmem (no bins, no smem atomics) ----
    float* ob = out + (size_t)b * NL * NC;

    #pragma unroll 1
    for (int g = 0; g < NG; g++) {
        __syncthreads();   // previous group's gather done -> sx reusable

        // transpose-store group g (pf holds it)
        #pragma unroll
        for (int h = 0; h < 2; h++) {
            int q = tid + h * THREADS;
            float4 a0 = pf[4 * h + 0], a1 = pf[4 * h + 1];
            float4 a2 = pf[4 * h + 2], a3 = pf[4 * h + 3];
            sts128(sx_base + swz(4 * q    ), a0.x, a1.x, a2.x, a3.x);
            sts128(sx_base + swz(4 * q + 1), a0.y, a1.y, a2.y, a3.y);
            sts128(sx_base + swz(4 * q + 2), a0.z, a1.z, a2.z, a3.z);
            sts128(sx_base + swz(4 * q + 3), a0.w, a1.w, a2.w, a3.w);
        }
        __syncthreads();   // sx ready for all

        // issue LDGs for group g+1 (overlap with gather below)
        if (g + 1 < NG) {
            const float* xp = xb + (size_t)(4 * (g + 1)) * HWP;
            #pragma unroll
            for (int h = 0; h < 2; h++) {
                int q = tid + h * THREADS;
                pf[4 * h + 0] = *(const float4*)(xp + 4 * q);
                pf[4 * h + 1] = *(const float4*)(xp + (size_t)HWP     + 4 * q);
                pf[4 * h + 2] = *(const float4*)(xp + (size_t)2 * HWP + 4 * q);
                pf[4 * h + 3] = *(const float4*)(xp + (size_t)3 * HWP + 4 * q);
            }
        }

        // gather 8 sorted entries, segmented float4 accumulation, red4 per run
        float4 a = lds128(sx_base + swz((int)(er[0] & 4095u)));
        unsigned int pl = er[0] >> 12;
        #pragma unroll
        for (int j = 1; j < 8; j++) {
            unsigned int l = er[j] >> 12;
            float4 vv = lds128(sx_base + swz((int)(er[j] & 4095u)));
            if (l != pl) {
                red4(ob + pl * NC + 4 * g, a.x, a.y, a.z, a.w);
                a = vv; pl = l;
            } else {
                a.x += vv.x; a.y += vv.y; a.z += vv.z; a.w += vv.w;
            }
        }
        red4(ob + pl * NC + 4 * g, a.x, a.y, a.z, a.w);
    }
}

__global__ void finalize_kernel(float* __restrict__ out) {
    int i = blockIdx.x * 256 + threadIdx.x;
    if (i >= NB * NL * NC) return;
    int bl = i / NC;
    int c = g_counts[bl];
    float cnt = (float)(c > 1 ? c : 1);
    out[i] = out[i] / cnt;
}

extern "C" void kernel_launch(void* const* d_in, const int* in_sizes, int n_in,
                              void* d_out, int out_size) {
    // Resolve input binding by element count — x has 134217728 elements,
    // label_maps has 1048576. Do not trust ordering.
    const float* x;
    const void*  lab;
    if (in_sizes[0] > in_sizes[1]) {
        x   = (const float*)d_in[0];
        lab = d_in[1];
    } else {
        x   = (const float*)d_in[1];
        lab = d_in[0];
    }
    float* out = (float*)d_out;

    cudaFuncSetAttribute(accum_kernel,
                         cudaFuncAttributeMaxDynamicSharedMemorySize, SMEM_BYTES);

    int ztot = NB * NL * NC;  // 262144
    zero_kernel<<<(ztot + 255) / 256, 256>>>(out, (const unsigned int*)lab);

    dim3 grid(HWP / TILE, NB);  // 64 x 4 = 256 CTAs, one wave at 2 CTA/SM
    accum_kernel<<<grid, THREADS, SMEM_BYTES>>>(x, lab, out);

    finalize_kernel<<<(ztot + 255) / 256, 256>>>(out);
}

// round 13
// speedup vs baseline: 2.5658x; 1.4547x over previous
#include <cuda_runtime.h>
#include <cuda_bf16.h>

#define NB 4
#define NC 128
#define HWP (512*512)
#define NL 512
#define TILE 4096
#define THREADS 512
#define PLANEB (TILE * 4)

// dynamic smem offsets (bytes)
#define OFF_RING   0                    // float ring[4][TILE]  = 65536
#define OFF_ENT    65536                // uint ent[TILE]       = 16384
#define OFF_CNT    81920                // int cnt[NL]          = 2048
#define OFF_START  83968                // int start[NL]        = 2048
#define OFF_CURSOR 86016                // int cursor[NL]       = 2048
#define OFF_WSUM   88064                // int wsum[16]         = 64
#define OFF_MBAR   88128                // uint64 mbar[4]       = 32
#define SMEM_BYTES 88160

__device__ int g_counts[NB * NL];
__device__ int g_lab64;   // 1 if labels are int64, 0 if int32

__device__ __forceinline__ void red4(float* p, float a, float b, float c, float d) {
    asm volatile("red.global.add.v4.f32 [%0], {%1,%2,%3,%4};"
                 :: "l"(p), "f"(a), "f"(b), "f"(c), "f"(d) : "memory");
}
__device__ __forceinline__ void mbar_init(unsigned int a, unsigned int cnt) {
    asm volatile("mbarrier.init.shared.b64 [%0], %1;" :: "r"(a), "r"(cnt) : "memory");
}
__device__ __forceinline__ void mbar_expect_tx(unsigned int a, unsigned int bytes) {
    asm volatile("mbarrier.arrive.expect_tx.shared.b64 _, [%0], %1;"
                 :: "r"(a), "r"(bytes) : "memory");
}
__device__ __forceinline__ void mbar_wait(unsigned int a, unsigned int parity) {
    asm volatile(
        "{\n\t"
        ".reg .pred P1;\n\t"
        "WAIT_LOOP_%=:\n\t"
        "mbarrier.try_wait.parity.acquire.cta.shared::cta.b64 P1, [%0], %1, 0x989680;\n\t"
        "@P1 bra.uni WAIT_DONE_%=;\n\t"
        "bra.uni WAIT_LOOP_%=;\n\t"
        "WAIT_DONE_%=:\n\t"
        "}"
        :: "r"(a), "r"(parity) : "memory");
}
__device__ __forceinline__ void bulk_g2s(unsigned int dst, const void* src,
                                         unsigned int bytes, unsigned int mbar) {
    asm volatile(
        "cp.async.bulk.shared::cta.global.mbarrier::complete_tx::bytes [%0], [%1], %2, [%3];"
        :: "r"(dst), "l"(src), "r"(bytes), "r"(mbar) : "memory");
}

__global__ void zero_kernel(float* __restrict__ out, const unsigned int* __restrict__ lab32) {
    int i = blockIdx.x * 256 + threadIdx.x;
    if (i == 0) {
        int is64 = 1;
        for (int k = 0; k < 128; k++) {
            if (lab32[2 * k + 1] != 0u || lab32[2 * k] >= 512u) { is64 = 0; break; }
        }
        g_lab64 = is64;
    }
    if (i < NB * NL * NC) out[i] = 0.0f;
    if (i < NB * NL) g_counts[i] = 0;
}

__global__ __launch_bounds__(THREADS, 2) void accum_kernel(
    const float* __restrict__ x,
    const void* __restrict__ lab_raw,
    float* __restrict__ out)
{
    extern __shared__ char smem[];
    float*        ring   = (float*)(smem + OFF_RING);
    unsigned int* ent    = (unsigned int*)(smem + OFF_ENT);
    int*          cnt    = (int*)(smem + OFF_CNT);
    int*          start_ = (int*)(smem + OFF_START);
    int*          cursor = (int*)(smem + OFF_CURSOR);
    int*          wsum   = (int*)(smem + OFF_WSUM);

    const int b    = blockIdx.y;
    const int p0   = blockIdx.x * TILE;
    const int tid  = threadIdx.x;
    const int lane = tid & 31;
    const int wid  = tid >> 5;

    const unsigned int smem_u32 = (unsigned int)__cvta_generic_to_shared(smem);
    const unsigned int ring_u32 = smem_u32 + OFF_RING;
    const unsigned int mbar_u32 = smem_u32 + OFF_MBAR;
    const float* xb = x + (size_t)b * NC * HWP + p0;

    // ---- init mbarriers; prefetch channels 0..3 into slots 0..3 (R9-proven) ----
    if (tid == 0) {
        #pragma unroll
        for (int s = 0; s < 4; s++) mbar_init(mbar_u32 + 8 * s, 1);
    }
    __syncthreads();
    if (tid == 0) {
        #pragma unroll
        for (int s = 0; s < 4; s++) {
            mbar_expect_tx(mbar_u32 + 8 * s, PLANEB);
            bulk_g2s(ring_u32 + s * PLANEB, xb + (size_t)s * HWP, PLANEB, mbar_u32 + 8 * s);
        }
    }

    // ---- labels into registers (8 per thread) — R9 verbatim ----
    int lab[8];
    if (g_lab64) {
        const long long* lb = (const long long*)lab_raw + (size_t)b * HWP + p0;
        #pragma unroll
        for (int h = 0; h < 2; h++) {
            int q = tid + h * THREADS;
            #pragma unroll
            for (int j = 0; j < 4; j++)
                lab[4 * h + j] = ((int)lb[4 * q + j]) & (NL - 1);
        }
    } else {
        const int4* lb = (const int4*)((const int*)lab_raw + (size_t)b * HWP + p0);
        #pragma unroll
        for (int h = 0; h < 2; h++) {
            int4 vv = lb[tid + h * THREADS];
            lab[4 * h + 0] = vv.x & (NL - 1);
            lab[4 * h + 1] = vv.y & (NL - 1);
            lab[4 * h + 2] = vv.z & (NL - 1);
            lab[4 * h + 3] = vv.w & (NL - 1);
        }
    }

    cnt[tid] = 0;                               // THREADS == NL
    __syncthreads();

    // ---- histogram ----
    #pragma unroll
    for (int k = 0; k < 8; k++) atomicAdd(&cnt[lab[k]], 1);
    __syncthreads();

    // ---- exclusive prefix sum over cnt[512] — all 512 threads, non-divergent ----
    int v = cnt[tid];
    int s = v;
    #pragma unroll
    for (int d = 1; d < 32; d <<= 1) {
        int n2 = __shfl_up_sync(0xffffffffu, s, d);
        if (lane >= d) s += n2;
    }
    if (lane == 31) wsum[wid] = s;
    __syncthreads();
    if (tid < 16) {
        int t = wsum[tid];
        #pragma unroll
        for (int d = 1; d < 16; d <<= 1) {
            int n2 = __shfl_up_sync(0x0000ffffu, t, d);
            if ((int)tid >= d) t += n2;
        }
        wsum[tid] = t;
    }
    __syncthreads();
    int excl = s - v + (wid ? wsum[wid - 1] : 0);
    start_[tid]  = excl;
    cursor[tid]  = excl;
    if (v) atomicAdd(&g_counts[b * NL + tid], v);
    __syncthreads();

    // ---- scatter packed entries (label<<12 | pixel), sorted by label ----
    #pragma unroll
    for (int h = 0; h < 2; h++) {
        #pragma unroll
        for (int j = 0; j < 4; j++) {
            int k   = 4 * h + j;
            int pix = 4 * (tid + h * THREADS) + j;
            int l   = lab[k];
            int pos = atomicAdd(&cursor[l], 1);
            ent[pos] = ((unsigned int)l << 12) | (unsigned int)pix;
        }
    }
    __syncthreads();

    // ---- each thread owns 8 consecutive sorted entries (perfectly balanced) ----
    unsigned int er[8];
    {
        uint4 e0 = *(const uint4*)(ent + 8 * tid);
        uint4 e1 = *(const uint4*)(ent + 8 * tid + 4);
        er[0] = e0.x; er[1] = e0.y; er[2] = e0.z; er[3] = e0.w;
        er[4] = e1.x; er[5] = e1.y; er[6] = e1.z; er[7] = e1.w;
    }

    // ---- channel loop: planar TMA ring (R9 scheme), per-entry float4 accumulators,
    //      R10-proven segmented merge -> red4 at group end ----
    float* ob = out + (size_t)b * NL * NC;

    #pragma unroll 1
    for (int g = 0; g < NC / 4; g++) {
        float4 acc[8];
        #pragma unroll
        for (int j = 0; j < 8; j++) acc[j] = make_float4(0.f, 0.f, 0.f, 0.f);

        const unsigned int par = (unsigned int)(g & 1);
        #pragma unroll
        for (int cc = 0; cc < 4; cc++) {
            const int c = 4 * g + cc;
            mbar_wait(mbar_u32 + 8 * cc, par);
            const float* buf = ring + cc * TILE;
            #pragma unroll
            for (int j = 0; j < 8; j++) {
                float vv = buf[er[j] & 4095u];
                if (cc == 0) acc[j].x += vv;
                if (cc == 1) acc[j].y += vv;
                if (cc == 2) acc[j].z += vv;
                if (cc == 3) acc[j].w += vv;
            }
            __syncthreads();   // all threads done with slot cc
            if (tid == 0 && c + 4 < NC) {
                mbar_expect_tx(mbar_u32 + 8 * cc, PLANEB);
                bulk_g2s(ring_u32 + cc * PLANEB, xb + (size_t)(c + 4) * HWP,
                         PLANEB, mbar_u32 + 8 * cc);
            }
        }

        // segmented merge over 8 entries (R10-proven pattern)
        float* obg = ob + 4 * g;
        float4 a = acc[0];
        unsigned int pl = er[0] >> 12;
        #pragma unroll
        for (int j = 1; j < 8; j++) {
            unsigned int l = er[j] >> 12;
            if (l != pl) {
                red4(obg + pl * NC, a.x, a.y, a.z, a.w);
                a = acc[j]; pl = l;
            } else {
                a.x += acc[j].x; a.y += acc[j].y; a.z += acc[j].z; a.w += acc[j].w;
            }
        }
        red4(obg + pl * NC, a.x, a.y, a.z, a.w);
    }
}

__global__ void finalize_kernel(float* __restrict__ out) {
    int i = blockIdx.x * 256 + threadIdx.x;
    if (i >= NB * NL * NC) return;
    int bl = i / NC;
    int c = g_counts[bl];
    float cnt = (float)(c > 1 ? c : 1);
    out[i] = out[i] / cnt;
}

extern "C" void kernel_launch(void* const* d_in, const int* in_sizes, int n_in,
                              void* d_out, int out_size) {
    // Resolve input binding by element count — do not trust ordering.
    const float* x;
    const void*  lab;
    if (in_sizes[0] > in_sizes[1]) {
        x   = (const float*)d_in[0];
        lab = d_in[1];
    } else {
        x   = (const float*)d_in[1];
        lab = d_in[0];
    }
    float* out = (float*)d_out;

    cudaFuncSetAttribute(accum_kernel,
                         cudaFuncAttributeMaxDynamicSharedMemorySize, SMEM_BYTES);

    int ztot = NB * NL * NC;  // 262144
    zero_kernel<<<(ztot + 255) / 256, 256>>>(out, (const unsigned int*)lab);

    dim3 grid(HWP / TILE, NB);  // 64 x 4 = 256 CTAs, single wave at 2 CTA/SM
    accum_kernel<<<grid, THREADS, SMEM_BYTES>>>(x, lab, out);

    finalize_kernel<<<(ztot + 255) / 256, 256>>>(out);
}

// round 14
// speedup vs baseline: 2.5705x; 1.0018x over previous
#include <cuda_runtime.h>
#include <cuda_bf16.h>

#define NB 4
#define NC 128
#define HWP (512*512)
#define NL 512
#define TILE 4096
#define THREADS 512
#define PLANEB (TILE * 4)

// dynamic smem offsets (bytes)
#define OFF_RING   0                    // float ring[4][TILE]  = 65536
#define OFF_ENT    65536                // uint ent[TILE]       = 16384
#define OFF_CNT    81920                // int cnt[NL]          = 2048
#define OFF_START  83968                // int start[NL]        = 2048
#define OFF_CURSOR 86016                // int cursor[NL]       = 2048
#define OFF_WSUM   88064                // int wsum[16]         = 64
#define OFF_MBAR   88128                // uint64 mbar[4]       = 32
#define SMEM_BYTES 88160

__device__ int g_counts[NB * NL];
__device__ int g_lab64;   // 1 if labels are int64, 0 if int32

__device__ __forceinline__ void red4(float* p, float a, float b, float c, float d) {
    asm volatile("red.global.add.v4.f32 [%0], {%1,%2,%3,%4};"
                 :: "l"(p), "f"(a), "f"(b), "f"(c), "f"(d) : "memory");
}
__device__ __forceinline__ void mbar_init(unsigned int a, unsigned int cnt) {
    asm volatile("mbarrier.init.shared.b64 [%0], %1;" :: "r"(a), "r"(cnt) : "memory");
}
__device__ __forceinline__ void mbar_expect_tx(unsigned int a, unsigned int bytes) {
    asm volatile("mbarrier.arrive.expect_tx.shared.b64 _, [%0], %1;"
                 :: "r"(a), "r"(bytes) : "memory");
}
__device__ __forceinline__ void mbar_wait(unsigned int a, unsigned int parity) {
    asm volatile(
        "{\n\t"
        ".reg .pred P1;\n\t"
        "WAIT_LOOP_%=:\n\t"
        "mbarrier.try_wait.parity.acquire.cta.shared::cta.b64 P1, [%0], %1, 0x989680;\n\t"
        "@P1 bra.uni WAIT_DONE_%=;\n\t"
        "bra.uni WAIT_LOOP_%=;\n\t"
        "WAIT_DONE_%=:\n\t"
        "}"
        :: "r"(a), "r"(parity) : "memory");
}
__device__ __forceinline__ void bulk_g2s(unsigned int dst, const void* src,
                                         unsigned int bytes, unsigned int mbar) {
    asm volatile(
        "cp.async.bulk.shared::cta.global.mbarrier::complete_tx::bytes [%0], [%1], %2, [%3];"
        :: "r"(dst), "l"(src), "r"(bytes), "r"(mbar) : "memory");
}

__global__ void zero_kernel(float* __restrict__ out, const unsigned int* __restrict__ lab32) {
    int i = blockIdx.x * 256 + threadIdx.x;
    if (i == 0) {
        int is64 = 1;
        for (int k = 0; k < 128; k++) {
            if (lab32[2 * k + 1] != 0u || lab32[2 * k] >= 512u) { is64 = 0; break; }
        }
        g_lab64 = is64;
    }
    if (i < NB * NL * NC) out[i] = 0.0f;
    if (i < NB * NL) g_counts[i] = 0;
}

__global__ __launch_bounds__(THREADS, 2) void accum_kernel(
    const float* __restrict__ x,
    const void* __restrict__ lab_raw,
    float* __restrict__ out)
{
    extern __shared__ char smem[];
    float*        ring   = (float*)(smem + OFF_RING);
    unsigned int* ent    = (unsigned int*)(smem + OFF_ENT);
    int*          cnt    = (int*)(smem + OFF_CNT);
    int*          start_ = (int*)(smem + OFF_START);
    int*          cursor = (int*)(smem + OFF_CURSOR);
    int*          wsum   = (int*)(smem + OFF_WSUM);

    const int b    = blockIdx.y;
    const int p0   = blockIdx.x * TILE;
    const int tid  = threadIdx.x;
    const int lane = tid & 31;
    const int wid  = tid >> 5;

    const unsigned int smem_u32 = (unsigned int)__cvta_generic_to_shared(smem);
    const unsigned int ring_u32 = smem_u32 + OFF_RING;
    const unsigned int mbar_u32 = smem_u32 + OFF_MBAR;
    const float* xb = x + (size_t)b * NC * HWP + p0;

    // ---- init mbarriers; prefetch channels 0..3 into slots 0..3 (R9-proven) ----
    if (tid == 0) {
        #pragma unroll
        for (int s = 0; s < 4; s++) mbar_init(mbar_u32 + 8 * s, 1);
    }
    __syncthreads();
    if (tid == 0) {
        #pragma unroll
        for (int s = 0; s < 4; s++) {
            mbar_expect_tx(mbar_u32 + 8 * s, PLANEB);
            bulk_g2s(ring_u32 + s * PLANEB, xb + (size_t)s * HWP, PLANEB, mbar_u32 + 8 * s);
        }
    }

    // ---- labels into registers (8 per thread) ----
    int lab[8];
    if (g_lab64) {
        const long long* lb = (const long long*)lab_raw + (size_t)b * HWP + p0;
        #pragma unroll
        for (int h = 0; h < 2; h++) {
            int q = tid + h * THREADS;
            #pragma unroll
            for (int j = 0; j < 4; j++)
                lab[4 * h + j] = ((int)lb[4 * q + j]) & (NL - 1);
        }
    } else {
        const int4* lb = (const int4*)((const int*)lab_raw + (size_t)b * HWP + p0);
        #pragma unroll
        for (int h = 0; h < 2; h++) {
            int4 vv = lb[tid + h * THREADS];
            lab[4 * h + 0] = vv.x & (NL - 1);
            lab[4 * h + 1] = vv.y & (NL - 1);
            lab[4 * h + 2] = vv.z & (NL - 1);
            lab[4 * h + 3] = vv.w & (NL - 1);
        }
    }

    cnt[tid] = 0;                               // THREADS == NL
    __syncthreads();

    // ---- histogram ----
    #pragma unroll
    for (int k = 0; k < 8; k++) atomicAdd(&cnt[lab[k]], 1);
    __syncthreads();

    // ---- exclusive prefix sum over cnt[512] — all 512 threads, non-divergent ----
    int v = cnt[tid];
    int s = v;
    #pragma unroll
    for (int d = 1; d < 32; d <<= 1) {
        int n2 = __shfl_up_sync(0xffffffffu, s, d);
        if (lane >= d) s += n2;
    }
    if (lane == 31) wsum[wid] = s;
    __syncthreads();
    if (tid < 16) {
        int t = wsum[tid];
        #pragma unroll
        for (int d = 1; d < 16; d <<= 1) {
            int n2 = __shfl_up_sync(0x0000ffffu, t, d);
            if ((int)tid >= d) t += n2;
        }
        wsum[tid] = t;
    }
    __syncthreads();
    int excl = s - v + (wid ? wsum[wid - 1] : 0);
    start_[tid]  = excl;
    cursor[tid]  = excl;
    if (v) atomicAdd(&g_counts[b * NL + tid], v);
    __syncthreads();

    // ---- scatter packed entries (label<<12 | pixel), sorted by label ----
    #pragma unroll
    for (int h = 0; h < 2; h++) {
        #pragma unroll
        for (int j = 0; j < 4; j++) {
            int k   = 4 * h + j;
            int pix = 4 * (tid + h * THREADS) + j;
            int l   = lab[k];
            int pos = atomicAdd(&cursor[l], 1);
            ent[pos] = ((unsigned int)l << 12) | (unsigned int)pix;
        }
    }
    __syncthreads();

    // ---- each thread owns 8 consecutive sorted entries (perfectly balanced) ----
    unsigned int er[8];
    int px[8];
    {
        uint4 e0 = *(const uint4*)(ent + 8 * tid);
        uint4 e1 = *(const uint4*)(ent + 8 * tid + 4);
        er[0] = e0.x; er[1] = e0.y; er[2] = e0.z; er[3] = e0.w;
        er[4] = e1.x; er[5] = e1.y; er[6] = e1.z; er[7] = e1.w;
    }
    #pragma unroll
    for (int j = 0; j < 8; j++) px[j] = (int)(er[j] & 4095u);

    // ---- channel loop: pairwise slot processing — 2 channels per sync ----
    float* ob = out + (size_t)b * NL * NC;
    float4 acc[8];

    #pragma unroll 1
    for (int gp = 0; gp < NC / 2; gp++) {
        const int c0    = 2 * gp;
        const int sbase = (gp & 1) * 2;                       // slots {0,1} or {2,3}
        const unsigned int par = (unsigned int)((gp >> 1) & 1);

        if ((gp & 1) == 0) {
            #pragma unroll
            for (int j = 0; j < 8; j++) acc[j] = make_float4(0.f, 0.f, 0.f, 0.f);
        }

        mbar_wait(mbar_u32 + 8 * sbase,       par);
        mbar_wait(mbar_u32 + 8 * (sbase + 1), par);

        const float* b0 = ring + sbase * TILE;
        const float* b1 = b0 + TILE;
        if ((gp & 1) == 0) {
            #pragma unroll
            for (int j = 0; j < 8; j++) {
                acc[j].x += b0[px[j]];
                acc[j].y += b1[px[j]];
            }
        } else {
            #pragma unroll
            for (int j = 0; j < 8; j++) {
                acc[j].z += b0[px[j]];
                acc[j].w += b1[px[j]];
            }
        }
        __syncthreads();   // all threads done with both slots

        if (tid == 0 && c0 + 4 < NC) {   // refill both slots (channels c0+4, c0+5)
            mbar_expect_tx(mbar_u32 + 8 * sbase, PLANEB);
            bulk_g2s(ring_u32 + sbase * PLANEB, xb + (size_t)(c0 + 4) * HWP,
                     PLANEB, mbar_u32 + 8 * sbase);
            mbar_expect_tx(mbar_u32 + 8 * (sbase + 1), PLANEB);
            bulk_g2s(ring_u32 + (sbase + 1) * PLANEB, xb + (size_t)(c0 + 5) * HWP,
                     PLANEB, mbar_u32 + 8 * (sbase + 1));
        }

        if (gp & 1) {   // group complete: segmented merge -> red4 per run
            float* obg = ob + 4 * (gp >> 1);
            float4 a = acc[0];
            unsigned int pl = er[0] >> 12;
            #pragma unroll
            for (int j = 1; j < 8; j++) {
                unsigned int l = er[j] >> 12;
                if (l != pl) {
                    red4(obg + pl * NC, a.x, a.y, a.z, a.w);
                    a = acc[j]; pl = l;
                } else {
                    a.x += acc[j].x; a.y += acc[j].y; a.z += acc[j].z; a.w += acc[j].w;
                }
            }
            red4(obg + pl * NC, a.x, a.y, a.z, a.w);
        }
    }
}

__global__ void finalize_kernel(float* __restrict__ out) {
    int i = blockIdx.x * 256 + threadIdx.x;
    if (i >= NB * NL * NC) return;
    int bl = i / NC;
    int c = g_counts[bl];
    float cnt = (float)(c > 1 ? c : 1);
    out[i] = out[i] / cnt;
}

extern "C" void kernel_launch(void* const* d_in, const int* in_sizes, int n_in,
                              void* d_out, int out_size) {
    // Resolve input binding by element count — do not trust ordering.
    const float* x;
    const void*  lab;
    if (in_sizes[0] > in_sizes[1]) {
        x   = (const float*)d_in[0];
        lab = d_in[1];
    } else {
        x   = (const float*)d_in[1];
        lab = d_in[0];
    }
    float* out = (float*)d_out;

    cudaFuncSetAttribute(accum_kernel,
                         cudaFuncAttributeMaxDynamicSharedMemorySize, SMEM_BYTES);

    int ztot = NB * NL * NC;  // 262144
    zero_kernel<<<(ztot + 255) / 256, 256>>>(out, (const unsigned int*)lab);

    dim3 grid(HWP / TILE, NB);  // 64 x 4 = 256 CTAs, single wave at 2 CTA/SM
    accum_kernel<<<grid, THREADS, SMEM_BYTES>>>(x, lab, out);

    finalize_kernel<<<(ztot + 255) / 256, 256>>>(out);
}